// round 13
// baseline (speedup 1.0000x reference)
#include <cuda_runtime.h>
#include <cuda_bf16.h>

#define N_NODES 50000
#define N_EDGES 600000
#define D 128
#define N_GRAPHS 500
#define SCAN_BLOCKS ((N_NODES + 1023) / 1024)   // 49

// ---------------- scratch (device globals: no runtime allocation allowed) ----
__device__ float          g_bufA[N_NODES * D];   // gemm<1> output (pool input)
__device__ float          g_bufB[N_NODES * D];   // gemm<0> output (h1)
__device__ unsigned short g_bufAh[N_NODES * D];  // aggregated rows, bf16 hi
__device__ unsigned short g_bufAl[N_NODES * D];  // aggregated rows, bf16 lo
__device__ int   g_deg_in[N_NODES];
__device__ int   g_deg_out[N_NODES];
__device__ float g_nsrc[N_NODES];
__device__ float g_ndst[N_NODES];
__device__ int   g_row_ptr[N_NODES + 1];
__device__ int   g_cursor[N_NODES];
__device__ int   g_csr_src[N_EDGES];

// ---------------- degree -----------------------------------------------------
__global__ void k_zero_deg() {
    int i = blockIdx.x * blockDim.x + threadIdx.x;
    if (i < N_NODES) { g_deg_in[i] = 0; g_deg_out[i] = 0; }
}

__global__ void k_degree(const int* __restrict__ src, const int* __restrict__ dst) {
    int e = blockIdx.x * blockDim.x + threadIdx.x;
    if (e < N_EDGES) {
        atomicAdd(&g_deg_out[src[e]], 1);
        atomicAdd(&g_deg_in[dst[e]], 1);
    }
}

// ---------------- single-kernel exclusive scan of deg_in ---------------------
__global__ void __launch_bounds__(1024) k_scan() {
    int tid = threadIdx.x;
    int base = blockIdx.x * 1024;
    int lane = tid & 31, w = tid >> 5;

    int part = 0;
    for (int j = tid; j < base; j += 1024) part += g_deg_in[j];

    int i = base + tid;
    int v = (i < N_NODES) ? g_deg_in[i] : 0;

    int x = v;
#pragma unroll
    for (int off = 1; off < 32; off <<= 1) {
        int y = __shfl_up_sync(0xffffffffu, x, off);
        if (lane >= off) x += y;
    }
#pragma unroll
    for (int off = 16; off > 0; off >>= 1)
        part += __shfl_down_sync(0xffffffffu, part, off);

    __shared__ int wt[32];
    __shared__ int rt[32];
    __shared__ int s_off;
    if (lane == 31) wt[w] = x;
    if (lane == 0)  rt[w] = part;
    __syncthreads();
    if (w == 0) {
        int t = wt[lane];
#pragma unroll
        for (int off = 1; off < 32; off <<= 1) {
            int y = __shfl_up_sync(0xffffffffu, t, off);
            if (lane >= off) t += y;
        }
        wt[lane] = t;
        int p = rt[lane];
#pragma unroll
        for (int off = 16; off > 0; off >>= 1)
            p += __shfl_down_sync(0xffffffffu, p, off);
        if (lane == 0) s_off = p;
    }
    __syncthreads();
    int warp_base = (w > 0) ? wt[w - 1] : 0;
    int excl = s_off + warp_base + x - v;
    if (i < N_NODES) {
        g_row_ptr[i] = excl;
        g_cursor[i]  = excl;
        g_ndst[i] = rsqrtf((float)max(g_deg_in[i], 1));
        g_nsrc[i] = rsqrtf((float)max(g_deg_out[i], 1));
    }
    if (i == 0) g_row_ptr[N_NODES] = N_EDGES;
}

// ---------------- CSR scatter (sort edges by dst) ---------------------------
__global__ void k_scatter(const int* __restrict__ src, const int* __restrict__ dst) {
    int e = blockIdx.x * blockDim.x + threadIdx.x;
    if (e < N_EDGES) {
        int d = dst[e];
        int p = atomicAdd(&g_cursor[d], 1);
        g_csr_src[p] = src[e];
    }
}

// ---------------- split helper ----------------------------------------------
__device__ __forceinline__ void bf16_split(float v, unsigned short& h, unsigned short& l) {
    __nv_bfloat16 hb = __float2bfloat16(v);
    float hf = __bfloat162float(hb);
    __nv_bfloat16 lb = __float2bfloat16(v - hf);
    h = __bfloat16_as_ushort(hb);
    l = __bfloat16_as_ushort(lb);
}

// ---------------- aggregation -> bf16 hi/lo split ---------------------------
// warp per dst node; lane owns a float4. 4-wide edge unroll. Output written
// as split bf16 (hi+lo) for the tensor-core GEMM.
template <int LAYER>
__global__ void __launch_bounds__(256) k_agg(const float* __restrict__ feats) {
    int warp = threadIdx.x >> 5, lane = threadIdx.x & 31;
    int node = blockIdx.x * 8 + warp;
    if (node >= N_NODES) return;
    const float* hin = (LAYER == 0) ? feats : (const float*)g_bufB;
    int b = g_row_ptr[node];
    int e = g_row_ptr[node + 1];
    const float4* h4 = (const float4*)hin;
    float4 acc = make_float4(0.f, 0.f, 0.f, 0.f);
    int i = b;
    for (; i + 3 < e; i += 4) {
        int s0 = g_csr_src[i];
        int s1 = g_csr_src[i + 1];
        int s2 = g_csr_src[i + 2];
        int s3 = g_csr_src[i + 3];
        float w0 = g_nsrc[s0];
        float w1 = g_nsrc[s1];
        float w2 = g_nsrc[s2];
        float w3 = g_nsrc[s3];
        float4 v0 = h4[s0 * 32 + lane];
        float4 v1 = h4[s1 * 32 + lane];
        float4 v2 = h4[s2 * 32 + lane];
        float4 v3 = h4[s3 * 32 + lane];
        acc.x += v0.x * w0; acc.y += v0.y * w0; acc.z += v0.z * w0; acc.w += v0.w * w0;
        acc.x += v1.x * w1; acc.y += v1.y * w1; acc.z += v1.z * w1; acc.w += v1.w * w1;
        acc.x += v2.x * w2; acc.y += v2.y * w2; acc.z += v2.z * w2; acc.w += v2.w * w2;
        acc.x += v3.x * w3; acc.y += v3.y * w3; acc.z += v3.z * w3; acc.w += v3.w * w3;
    }
    for (; i < e; i++) {
        int s0 = g_csr_src[i];
        float w0 = g_nsrc[s0];
        float4 v0 = h4[s0 * 32 + lane];
        acc.x += v0.x * w0; acc.y += v0.y * w0; acc.z += v0.z * w0; acc.w += v0.w * w0;
    }
    float nd = g_ndst[node];
    acc = make_float4(acc.x * nd, acc.y * nd, acc.z * nd, acc.w * nd);
    ushort4 hh, ll;
    bf16_split(acc.x, hh.x, ll.x);
    bf16_split(acc.y, hh.y, ll.y);
    bf16_split(acc.z, hh.z, ll.z);
    bf16_split(acc.w, hh.w, ll.w);
    ((ushort4*)g_bufAh)[node * 32 + lane] = hh;
    ((ushort4*)g_bufAl)[node * 32 + lane] = ll;
}

// ---------------- tensor-core GEMM + bias + ReLU ----------------------------
// out = relu( A @ W + b ), A given as split bf16 (g_bufAh/g_bufAl).
// Block: 256 thr = 8 warps; tile 128 nodes x 128 j; warp w owns rows
// [nb + 16w, nb + 16w + 16), full 128 j (16 n-tiles of 8).
// W transposed+split in smem: Wsh[j][k_tile 64], row stride 72 ushorts
// (=36 uints) -> fragment-load banks 4g+t, conflict-free.
// mma.sync.m16n8k16 bf16, split products: Ah*Wh + Ah*Wl + Al*Wh.
template <int LAYER>
__global__ void __launch_bounds__(256) k_gemm(const float* __restrict__ W,
                                              const float* __restrict__ bias) {
    __shared__ unsigned short WshH[128 * 72];   // 18KB
    __shared__ unsigned short WshL[128 * 72];   // 18KB
    int tid = threadIdx.x;
    int w = tid >> 5, lane = tid & 31;
    int g = lane >> 2, t = lane & 3;
    int nb = blockIdx.x * 128;
    int r0 = nb + w * 16 + g;
    int r1 = r0 + 8;
    float* out = (LAYER == 0) ? g_bufB : g_bufA;

    const float4* W4 = (const float4*)W;
    const unsigned int* AH = (const unsigned int*)g_bufAh;  // row = 64 uints
    const unsigned int* AL = (const unsigned int*)g_bufAl;
    const unsigned int* WH32 = (const unsigned int*)WshH;
    const unsigned int* WL32 = (const unsigned int*)WshL;

    float c[16][4];
#pragma unroll
    for (int n = 0; n < 16; n++) { c[n][0] = c[n][1] = c[n][2] = c[n][3] = 0.f; }

#pragma unroll
    for (int ktile = 0; ktile < 2; ktile++) {
        // --- transpose + split W[ktile*64 .. +64)[0..128) into Wsh[j][k] ---
#pragma unroll
        for (int i = 0; i < 8; i++) {
            int idx = tid + 256 * i;          // 0..2047
            int kr = idx >> 5;                // 0..63
            int jq = (idx & 31) * 4;          // j quad
            float4 wv = W4[(ktile * 64 + kr) * 32 + (idx & 31)];
            unsigned short h, l;
            bf16_split(wv.x, h, l); WshH[(jq + 0) * 72 + kr] = h; WshL[(jq + 0) * 72 + kr] = l;
            bf16_split(wv.y, h, l); WshH[(jq + 1) * 72 + kr] = h; WshL[(jq + 1) * 72 + kr] = l;
            bf16_split(wv.z, h, l); WshH[(jq + 2) * 72 + kr] = h; WshL[(jq + 2) * 72 + kr] = l;
            bf16_split(wv.w, h, l); WshH[(jq + 3) * 72 + kr] = h; WshL[(jq + 3) * 72 + kr] = l;
        }
        __syncthreads();

#pragma unroll
        for (int ks = 0; ks < 4; ks++) {
            // A fragments from global (L2-hot), k = ktile*64 + ks*16 + {2t, 2t+1, +8}
            unsigned int kidx = ktile * 32 + ks * 8 + t;   // uint units
            unsigned int a0h = 0, a1h = 0, a2h = 0, a3h = 0;
            unsigned int a0l = 0, a1l = 0, a2l = 0, a3l = 0;
            if (r0 < N_NODES) {
                a0h = AH[r0 * 64 + kidx];      a2h = AH[r0 * 64 + kidx + 4];
                a0l = AL[r0 * 64 + kidx];      a2l = AL[r0 * 64 + kidx + 4];
            }
            if (r1 < N_NODES) {
                a1h = AH[r1 * 64 + kidx];      a3h = AH[r1 * 64 + kidx + 4];
                a1l = AL[r1 * 64 + kidx];      a3l = AL[r1 * 64 + kidx + 4];
            }
            int ksu = ks * 8;   // uint offset of this k-step within the tile
#pragma unroll
            for (int nt = 0; nt < 16; nt++) {
                int rowb = (nt * 8 + g) * 36 + ksu + t;
                unsigned int b0h = WH32[rowb];
                unsigned int b1h = WH32[rowb + 4];
                unsigned int b0l = WL32[rowb];
                unsigned int b1l = WL32[rowb + 4];
                asm("mma.sync.aligned.m16n8k16.row.col.f32.bf16.bf16.f32 "
                    "{%0,%1,%2,%3}, {%4,%5,%6,%7}, {%8,%9}, {%0,%1,%2,%3};"
                    : "+f"(c[nt][0]), "+f"(c[nt][1]), "+f"(c[nt][2]), "+f"(c[nt][3])
                    : "r"(a0h), "r"(a1h), "r"(a2h), "r"(a3h), "r"(b0h), "r"(b1h));
                asm("mma.sync.aligned.m16n8k16.row.col.f32.bf16.bf16.f32 "
                    "{%0,%1,%2,%3}, {%4,%5,%6,%7}, {%8,%9}, {%0,%1,%2,%3};"
                    : "+f"(c[nt][0]), "+f"(c[nt][1]), "+f"(c[nt][2]), "+f"(c[nt][3])
                    : "r"(a0h), "r"(a1h), "r"(a2h), "r"(a3h), "r"(b0l), "r"(b1l));
                asm("mma.sync.aligned.m16n8k16.row.col.f32.bf16.bf16.f32 "
                    "{%0,%1,%2,%3}, {%4,%5,%6,%7}, {%8,%9}, {%0,%1,%2,%3};"
                    : "+f"(c[nt][0]), "+f"(c[nt][1]), "+f"(c[nt][2]), "+f"(c[nt][3])
                    : "r"(a0l), "r"(a1l), "r"(a2l), "r"(a3l), "r"(b0h), "r"(b1h));
            }
        }
        __syncthreads();
    }

    // epilogue: bias + relu, c0/c1 -> row r0, c2/c3 -> row r1; cols nt*8+2t(+1)
#pragma unroll
    for (int nt = 0; nt < 16; nt++) {
        int jn = nt * 8 + 2 * t;
        float2 bv = *(const float2*)&bias[jn];
        if (r0 < N_NODES) {
            float2 o;
            o.x = fmaxf(c[nt][0] + bv.x, 0.f);
            o.y = fmaxf(c[nt][1] + bv.y, 0.f);
            *(float2*)&out[r0 * D + jn] = o;
        }
        if (r1 < N_NODES) {
            float2 o;
            o.x = fmaxf(c[nt][2] + bv.x, 0.f);
            o.y = fmaxf(c[nt][3] + bv.y, 0.f);
            *(float2*)&out[r1 * D + jn] = o;
        }
    }
}

// ---------------- per-graph mean pooling (graph_ids sorted) -----------------
__global__ void k_pool(const int* __restrict__ gid, float* __restrict__ out) {
    int g = blockIdx.x;
    int j = threadIdx.x;      // 128 threads = feature dims
    int lo = 0, hi = N_NODES;
    while (lo < hi) { int mid = (lo + hi) >> 1; if (gid[mid] < g) lo = mid + 1; else hi = mid; }
    int s = lo;
    lo = s; hi = N_NODES;
    while (lo < hi) { int mid = (lo + hi) >> 1; if (gid[mid] < g + 1) lo = mid + 1; else hi = mid; }
    int e = lo;
    float sum = 0.f;
    for (int n = s; n < e; n++) sum += g_bufA[n * D + j];
    float cnt = (float)max(e - s, 1);
    out[g * D + j] = sum / cnt;
}

// ---------------- launch ----------------------------------------------------
extern "C" void kernel_launch(void* const* d_in, const int* in_sizes, int n_in,
                              void* d_out, int out_size) {
    const float* feats = (const float*)d_in[0];
    const float* W1    = (const float*)d_in[1];
    const float* b1    = (const float*)d_in[2];
    const float* W2    = (const float*)d_in[3];
    const float* b2    = (const float*)d_in[4];
    const int*   src   = (const int*)d_in[5];
    const int*   dst   = (const int*)d_in[6];
    const int*   gid   = (const int*)d_in[7];
    float* out = (float*)d_out;

    const int TB = 256;
    int nodeBlocks = (N_NODES + TB - 1) / TB;     // 196
    int edgeBlocks = (N_EDGES + TB - 1) / TB;     // 2344
    int aggBlocks  = (N_NODES + 7) / 8;           // 6250
    int gemmBlocks = (N_NODES + 127) / 128;       // 391

    // graph preprocessing (degrees + one-shot scan/norms + CSR by dst)
    k_zero_deg<<<nodeBlocks, TB>>>();
    k_degree<<<edgeBlocks, TB>>>(src, dst);
    k_scan<<<SCAN_BLOCKS, 1024>>>();
    k_scatter<<<edgeBlocks, TB>>>(src, dst);

    // layer 1
    k_agg<0><<<aggBlocks, TB>>>(feats);
    k_gemm<0><<<gemmBlocks, TB>>>(W1, b1);        // -> g_bufB
    // layer 2
    k_agg<1><<<aggBlocks, TB>>>(feats);
    k_gemm<1><<<gemmBlocks, TB>>>(W2, b2);        // -> g_bufA

    // pooling
    k_pool<<<N_GRAPHS, D>>>(gid, out);
}

// round 14
// speedup vs baseline: 1.0765x; 1.0765x over previous
#include <cuda_runtime.h>
#include <cuda_bf16.h>

#define N_NODES 50000
#define N_EDGES 600000
#define D 128
#define N_GRAPHS 500
#define SCAN_BLOCKS ((N_NODES + 1023) / 1024)   // 49

// ---------------- scratch (device globals: no runtime allocation allowed) ----
__device__ float g_bufA[N_NODES * D];   // aggregation result (m * norm_dst)
__device__ float g_bufB[N_NODES * D];   // layer output h
__device__ int   g_deg_in[N_NODES];
__device__ int   g_deg_out[N_NODES];
__device__ float g_nsrc[N_NODES];
__device__ float g_ndst[N_NODES];
__device__ int   g_row_ptr[N_NODES + 1];
__device__ int   g_cursor[N_NODES];
__device__ int   g_csr_src[N_EDGES];

// ---------------- degree -----------------------------------------------------
__global__ void k_zero_deg() {
    int i = blockIdx.x * blockDim.x + threadIdx.x;
    if (i < N_NODES) { g_deg_in[i] = 0; g_deg_out[i] = 0; }
}

__global__ void k_degree(const int* __restrict__ src, const int* __restrict__ dst) {
    int e = blockIdx.x * blockDim.x + threadIdx.x;
    if (e < N_EDGES) {
        atomicAdd(&g_deg_out[src[e]], 1);
        atomicAdd(&g_deg_in[dst[e]], 1);
    }
}

// ---------------- single-kernel exclusive scan of deg_in ---------------------
// Block b computes its own global offset by summing deg_in[0 .. b*1024)
// directly (L2-resident) -- no inter-block dependency. Also writes cursor
// and both norms.
__global__ void __launch_bounds__(1024) k_scan() {
    int tid = threadIdx.x;
    int base = blockIdx.x * 1024;
    int lane = tid & 31, w = tid >> 5;

    int part = 0;
    for (int j = tid; j < base; j += 1024) part += g_deg_in[j];

    int i = base + tid;
    int v = (i < N_NODES) ? g_deg_in[i] : 0;

    int x = v;
#pragma unroll
    for (int off = 1; off < 32; off <<= 1) {
        int y = __shfl_up_sync(0xffffffffu, x, off);
        if (lane >= off) x += y;
    }
#pragma unroll
    for (int off = 16; off > 0; off >>= 1)
        part += __shfl_down_sync(0xffffffffu, part, off);

    __shared__ int wt[32];
    __shared__ int rt[32];
    __shared__ int s_off;
    if (lane == 31) wt[w] = x;
    if (lane == 0)  rt[w] = part;
    __syncthreads();
    if (w == 0) {
        int t = wt[lane];
#pragma unroll
        for (int off = 1; off < 32; off <<= 1) {
            int y = __shfl_up_sync(0xffffffffu, t, off);
            if (lane >= off) t += y;
        }
        wt[lane] = t;
        int p = rt[lane];
#pragma unroll
        for (int off = 16; off > 0; off >>= 1)
            p += __shfl_down_sync(0xffffffffu, p, off);
        if (lane == 0) s_off = p;
    }
    __syncthreads();
    int warp_base = (w > 0) ? wt[w - 1] : 0;
    int excl = s_off + warp_base + x - v;
    if (i < N_NODES) {
        g_row_ptr[i] = excl;
        g_cursor[i]  = excl;
        g_ndst[i] = rsqrtf((float)max(g_deg_in[i], 1));
        g_nsrc[i] = rsqrtf((float)max(g_deg_out[i], 1));
    }
    if (i == 0) g_row_ptr[N_NODES] = N_EDGES;
}

// ---------------- CSR scatter (sort edges by dst) ---------------------------
__global__ void k_scatter(const int* __restrict__ src, const int* __restrict__ dst) {
    int e = blockIdx.x * blockDim.x + threadIdx.x;
    if (e < N_EDGES) {
        int d = dst[e];
        int p = atomicAdd(&g_cursor[d], 1);
        g_csr_src[p] = src[e];
    }
}

// ---------------- aggregation: g_bufA[d] = ndst[d] * sum_in(h[s]*nsrc[s]) ---
// warp per dst node; lane owns a float4. 4-wide edge unroll -> MLP=4 on the
// L2-hit chain; near the L2 bandwidth floor.
template <int LAYER>
__global__ void __launch_bounds__(256) k_agg(const float* __restrict__ feats) {
    int warp = threadIdx.x >> 5, lane = threadIdx.x & 31;
    int node = blockIdx.x * 8 + warp;
    if (node >= N_NODES) return;
    const float* hin = (LAYER == 0) ? feats : (const float*)g_bufB;
    int b = g_row_ptr[node];
    int e = g_row_ptr[node + 1];
    const float4* h4 = (const float4*)hin;
    float4 acc = make_float4(0.f, 0.f, 0.f, 0.f);
    int i = b;
    for (; i + 3 < e; i += 4) {
        int s0 = g_csr_src[i];
        int s1 = g_csr_src[i + 1];
        int s2 = g_csr_src[i + 2];
        int s3 = g_csr_src[i + 3];
        float w0 = g_nsrc[s0];
        float w1 = g_nsrc[s1];
        float w2 = g_nsrc[s2];
        float w3 = g_nsrc[s3];
        float4 v0 = h4[s0 * 32 + lane];
        float4 v1 = h4[s1 * 32 + lane];
        float4 v2 = h4[s2 * 32 + lane];
        float4 v3 = h4[s3 * 32 + lane];
        acc.x += v0.x * w0; acc.y += v0.y * w0; acc.z += v0.z * w0; acc.w += v0.w * w0;
        acc.x += v1.x * w1; acc.y += v1.y * w1; acc.z += v1.z * w1; acc.w += v1.w * w1;
        acc.x += v2.x * w2; acc.y += v2.y * w2; acc.z += v2.z * w2; acc.w += v2.w * w2;
        acc.x += v3.x * w3; acc.y += v3.y * w3; acc.z += v3.z * w3; acc.w += v3.w * w3;
    }
    for (; i < e; i++) {
        int s0 = g_csr_src[i];
        float w0 = g_nsrc[s0];
        float4 v0 = h4[s0 * 32 + lane];
        acc.x += v0.x * w0; acc.y += v0.y * w0; acc.z += v0.z * w0; acc.w += v0.w * w0;
    }
    float nd = g_ndst[node];
    ((float4*)g_bufA)[node * 32 + lane] =
        make_float4(acc.x * nd, acc.y * nd, acc.z * nd, acc.w * nd);
}

// ---------------- GEMM + bias + ReLU: g_bufB = relu(g_bufA @ W + b) ---------
// 512 threads, 128 nodes/block (W tile reused across 2x nodes vs R11 ->
// half the W-fill traffic and half the blocks). Thread tile = 8 nodes x 4 j.
// k tiled in 4 chunks of 32: Wsh 16KB + Ash 16KB = 32KB static smem.
// Inner loop identical to the measured-best R5/R11 FFMA2 loop.
__global__ void __launch_bounds__(512) k_gemm(const float* __restrict__ W,
                                              const float* __restrict__ bias) {
    __shared__ float Wsh[32 * 128];       // [k_local][j]
    __shared__ float Ash[128 * 32];       // [node][k_local]
    int tid = threadIdx.x;
    int jt = tid & 31;          // j quad: columns 4*jt .. 4*jt+3
    int nt = tid >> 5;          // node group 0..15 (8 nodes each)
    int nb = blockIdx.x * 128;

    const float4* W4 = (const float4*)W;
    const float4* A4 = (const float4*)g_bufA;
    float4* Wsh4 = (float4*)Wsh;
    float4* Ash4 = (float4*)Ash;

    unsigned long long acc01[8], acc23[8];
#pragma unroll
    for (int i = 0; i < 8; i++) { acc01[i] = 0ull; acc23[i] = 0ull; }

#pragma unroll
    for (int kt = 0; kt < 4; kt++) {
        // Wsh: rows kt*32 .. kt*32+31, all 128 j = 1024 float4 (512 thr x 2)
#pragma unroll
        for (int i = 0; i < 2; i++) {
            int idx = tid + 512 * i;                    // 0..1023
            Wsh4[idx] = W4[(kt * 32 + (idx >> 5)) * 32 + (idx & 31)];
        }
        // Ash: 128 nodes x 32 k = 1024 float4 (8 float4 per node)
#pragma unroll
        for (int i = 0; i < 2; i++) {
            int idx = tid + 512 * i;                    // 0..1023
            int n = nb + (idx >> 3);
            Ash4[idx] = (n < N_NODES) ? A4[n * 32 + kt * 8 + (idx & 7)]
                                      : make_float4(0.f, 0.f, 0.f, 0.f);
        }
        __syncthreads();

#pragma unroll 4
        for (int k = 0; k < 32; k += 2) {
            ulonglong2 wa = *(const ulonglong2*)&Wsh[k * 128 + jt * 4];
            ulonglong2 wb = *(const ulonglong2*)&Wsh[(k + 1) * 128 + jt * 4];
#pragma unroll
            for (int i = 0; i < 8; i++) {
                const float* arow = &Ash[(nt * 8 + i) * 32 + k];
                unsigned int a0 = __float_as_uint(arow[0]);
                unsigned int a1 = __float_as_uint(arow[1]);
                unsigned long long a00, a11;
                asm("mov.b64 %0, {%1, %1};" : "=l"(a00) : "r"(a0));
                asm("mov.b64 %0, {%1, %1};" : "=l"(a11) : "r"(a1));
                asm("fma.rn.f32x2 %0, %1, %2, %0;" : "+l"(acc01[i]) : "l"(a00), "l"(wa.x));
                asm("fma.rn.f32x2 %0, %1, %2, %0;" : "+l"(acc23[i]) : "l"(a00), "l"(wa.y));
                asm("fma.rn.f32x2 %0, %1, %2, %0;" : "+l"(acc01[i]) : "l"(a11), "l"(wb.x));
                asm("fma.rn.f32x2 %0, %1, %2, %0;" : "+l"(acc23[i]) : "l"(a11), "l"(wb.y));
            }
        }
        __syncthreads();
    }

    float4 bv = __ldg(&((const float4*)bias)[jt]);
#pragma unroll
    for (int i = 0; i < 8; i++) {
        int n = nb + nt * 8 + i;
        if (n < N_NODES) {
            unsigned int r01lo, r01hi, r23lo, r23hi;
            asm("mov.b64 {%0, %1}, %2;" : "=r"(r01lo), "=r"(r01hi) : "l"(acc01[i]));
            asm("mov.b64 {%0, %1}, %2;" : "=r"(r23lo), "=r"(r23hi) : "l"(acc23[i]));
            float4 r;
            r.x = fmaxf(__uint_as_float(r01lo) + bv.x, 0.f);
            r.y = fmaxf(__uint_as_float(r01hi) + bv.y, 0.f);
            r.z = fmaxf(__uint_as_float(r23lo) + bv.z, 0.f);
            r.w = fmaxf(__uint_as_float(r23hi) + bv.w, 0.f);
            ((float4*)g_bufB)[n * 32 + jt] = r;
        }
    }
}

// ---------------- per-graph mean pooling (graph_ids sorted) -----------------
__global__ void k_pool(const int* __restrict__ gid, float* __restrict__ out) {
    int g = blockIdx.x;
    int j = threadIdx.x;      // 128 threads = feature dims
    int lo = 0, hi = N_NODES;
    while (lo < hi) { int mid = (lo + hi) >> 1; if (gid[mid] < g) lo = mid + 1; else hi = mid; }
    int s = lo;
    lo = s; hi = N_NODES;
    while (lo < hi) { int mid = (lo + hi) >> 1; if (gid[mid] < g + 1) lo = mid + 1; else hi = mid; }
    int e = lo;
    float sum = 0.f;
    for (int n = s; n < e; n++) sum += g_bufB[n * D + j];
    float cnt = (float)max(e - s, 1);
    out[g * D + j] = sum / cnt;
}

// ---------------- launch ----------------------------------------------------
extern "C" void kernel_launch(void* const* d_in, const int* in_sizes, int n_in,
                              void* d_out, int out_size) {
    const float* feats = (const float*)d_in[0];
    const float* W1    = (const float*)d_in[1];
    const float* b1    = (const float*)d_in[2];
    const float* W2    = (const float*)d_in[3];
    const float* b2    = (const float*)d_in[4];
    const int*   src   = (const int*)d_in[5];
    const int*   dst   = (const int*)d_in[6];
    const int*   gid   = (const int*)d_in[7];
    float* out = (float*)d_out;

    const int TB = 256;
    int nodeBlocks = (N_NODES + TB - 1) / TB;     // 196
    int edgeBlocks = (N_EDGES + TB - 1) / TB;     // 2344
    int aggBlocks  = (N_NODES + 7) / 8;           // 6250
    int gemmBlocks = (N_NODES + 127) / 128;       // 391

    // graph preprocessing (degrees + one-shot scan/norms + CSR by dst)
    k_zero_deg<<<nodeBlocks, TB>>>();
    k_degree<<<edgeBlocks, TB>>>(src, dst);
    k_scan<<<SCAN_BLOCKS, 1024>>>();
    k_scatter<<<edgeBlocks, TB>>>(src, dst);

    // layer 1
    k_agg<0><<<aggBlocks, TB>>>(feats);
    k_gemm<<<gemmBlocks, 512>>>(W1, b1);
    // layer 2
    k_agg<1><<<aggBlocks, TB>>>(feats);
    k_gemm<<<gemmBlocks, 512>>>(W2, b2);

    // pooling
    k_pool<<<N_GRAPHS, D>>>(gid, out);
}

// round 15
// speedup vs baseline: 1.1272x; 1.0470x over previous
#include <cuda_runtime.h>
#include <cuda_bf16.h>

#define N_NODES 50000
#define N_EDGES 600000
#define D 128
#define N_GRAPHS 500
#define SCAN_BLOCKS ((N_NODES + 1023) / 1024)   // 49

// ---------------- scratch (device globals: no runtime allocation allowed) ----
__device__ float g_bufA[N_NODES * D];   // aggregation result (m * norm_dst)
__device__ float g_bufB[N_NODES * D];   // layer output h
__device__ int   g_deg_in[N_NODES];
__device__ int   g_deg_out[N_NODES];
__device__ float g_nsrc[N_NODES];
__device__ float g_ndst[N_NODES];
__device__ int   g_row_ptr[N_NODES + 1];
__device__ int   g_cursor[N_NODES];
__device__ int   g_csr_src[N_EDGES];
__device__ int   g_part[SCAN_BLOCKS];   // per-block totals (raw)

// ---------------- degree -----------------------------------------------------
__global__ void k_zero_deg() {
    int i = blockIdx.x * blockDim.x + threadIdx.x;
    if (i < N_NODES) { g_deg_in[i] = 0; g_deg_out[i] = 0; }
}

__global__ void k_degree(const int* __restrict__ src, const int* __restrict__ dst) {
    int e = blockIdx.x * blockDim.x + threadIdx.x;
    if (e < N_EDGES) {
        atomicAdd(&g_deg_out[src[e]], 1);
        atomicAdd(&g_deg_in[dst[e]], 1);
    }
}

// ---------------- parallel exclusive scan of deg_in -------------------------
// Phase A: per-block (1024) exclusive scan -> g_row_ptr local, raw totals -> g_part
__global__ void __launch_bounds__(1024) k_scan_a() {
    int tid = threadIdx.x;
    int i = blockIdx.x * 1024 + tid;
    int v = (i < N_NODES) ? g_deg_in[i] : 0;
    int lane = tid & 31, w = tid >> 5;

    int x = v;
#pragma unroll
    for (int off = 1; off < 32; off <<= 1) {
        int y = __shfl_up_sync(0xffffffffu, x, off);
        if (lane >= off) x += y;
    }
    __shared__ int wt[32];
    if (lane == 31) wt[w] = x;
    __syncthreads();
    if (w == 0) {
        int t = wt[lane];
#pragma unroll
        for (int off = 1; off < 32; off <<= 1) {
            int y = __shfl_up_sync(0xffffffffu, t, off);
            if (lane >= off) t += y;
        }
        wt[lane] = t;
    }
    __syncthreads();
    int warp_base = (w > 0) ? wt[w - 1] : 0;
    int excl = warp_base + x - v;
    if (i < N_NODES) g_row_ptr[i] = excl;
    if (tid == 1023) g_part[blockIdx.x] = excl + v;   // raw block total
}

// Phase C: each block reduces g_part[0..bid) itself, adds offset, writes
// final row_ptr + cursor, computes norms.
__global__ void __launch_bounds__(1024) k_scan_c() {
    __shared__ int s_off;
    int tid = threadIdx.x;
    if (tid < 32) {
        int p = 0;
        for (int j = tid; j < blockIdx.x; j += 32) p += g_part[j];
#pragma unroll
        for (int off = 16; off > 0; off >>= 1)
            p += __shfl_down_sync(0xffffffffu, p, off);
        if (tid == 0) s_off = p;
    }
    __syncthreads();
    int i = blockIdx.x * 1024 + tid;
    if (i >= N_NODES) return;
    int rp = g_row_ptr[i] + s_off;
    g_row_ptr[i] = rp;
    g_cursor[i]  = rp;
    g_ndst[i] = rsqrtf((float)max(g_deg_in[i], 1));
    g_nsrc[i] = rsqrtf((float)max(g_deg_out[i], 1));
    if (i == 0) g_row_ptr[N_NODES] = N_EDGES;
}

// ---------------- CSR scatter (sort edges by dst) ---------------------------
__global__ void k_scatter(const int* __restrict__ src, const int* __restrict__ dst) {
    int e = blockIdx.x * blockDim.x + threadIdx.x;
    if (e < N_EDGES) {
        int d = dst[e];
        int p = atomicAdd(&g_cursor[d], 1);
        g_csr_src[p] = src[e];
    }
}

// ---------------- aggregation: g_bufA[d] = ndst[d] * sum_in(h[s]*nsrc[s]) ---
// warp per dst node; lane owns a float4. 4-wide edge unroll -> MLP=4 on the
// L2-hit chain; at the LTS bandwidth cap.
template <int LAYER>
__global__ void __launch_bounds__(256) k_agg(const float* __restrict__ feats) {
    int warp = threadIdx.x >> 5, lane = threadIdx.x & 31;
    int node = blockIdx.x * 8 + warp;
    if (node >= N_NODES) return;
    const float* hin = (LAYER == 0) ? feats : (const float*)g_bufB;
    int b = g_row_ptr[node];
    int e = g_row_ptr[node + 1];
    const float4* h4 = (const float4*)hin;
    float4 acc = make_float4(0.f, 0.f, 0.f, 0.f);
    int i = b;
    for (; i + 3 < e; i += 4) {
        int s0 = g_csr_src[i];
        int s1 = g_csr_src[i + 1];
        int s2 = g_csr_src[i + 2];
        int s3 = g_csr_src[i + 3];
        float w0 = g_nsrc[s0];
        float w1 = g_nsrc[s1];
        float w2 = g_nsrc[s2];
        float w3 = g_nsrc[s3];
        float4 v0 = h4[s0 * 32 + lane];
        float4 v1 = h4[s1 * 32 + lane];
        float4 v2 = h4[s2 * 32 + lane];
        float4 v3 = h4[s3 * 32 + lane];
        acc.x += v0.x * w0; acc.y += v0.y * w0; acc.z += v0.z * w0; acc.w += v0.w * w0;
        acc.x += v1.x * w1; acc.y += v1.y * w1; acc.z += v1.z * w1; acc.w += v1.w * w1;
        acc.x += v2.x * w2; acc.y += v2.y * w2; acc.z += v2.z * w2; acc.w += v2.w * w2;
        acc.x += v3.x * w3; acc.y += v3.y * w3; acc.z += v3.z * w3; acc.w += v3.w * w3;
    }
    for (; i < e; i++) {
        int s0 = g_csr_src[i];
        float w0 = g_nsrc[s0];
        float4 v0 = h4[s0 * 32 + lane];
        acc.x += v0.x * w0; acc.y += v0.y * w0; acc.z += v0.z * w0; acc.w += v0.w * w0;
    }
    float nd = g_ndst[node];
    ((float4*)g_bufA)[node * 32 + lane] =
        make_float4(acc.x * nd, acc.y * nd, acc.z * nd, acc.w * nd);
}

// ---------------- GEMM + bias + ReLU: g_bufB = relu(g_bufA @ W + b) ---------
// Best-measured config (R5/R8/R11): 256 threads, 64 nodes/block, thread tile
// = 8 nodes x 4 j. FFMA2 mainloop with dup-pack MOVs (dual-issue into the
// spare slots of the rt-2 FFMA2 stream). 48KB static smem, 2 k-tiles.
__global__ void __launch_bounds__(256) k_gemm(const float* __restrict__ W,
                                              const float* __restrict__ bias) {
    __shared__ float Wsh[64 * 128];
    __shared__ float Ash[64 * 64];
    int tid = threadIdx.x;
    int jt = tid & 31;          // j quad: columns 4*jt .. 4*jt+3
    int nt = tid >> 5;          // node group 0..7 (8 nodes each)
    int nb = blockIdx.x * 64;

    const float4* W4 = (const float4*)W;
    const float4* A4 = (const float4*)g_bufA;
    float4* Wsh4 = (float4*)Wsh;
    float4* Ash4 = (float4*)Ash;

    unsigned long long acc01[8], acc23[8];
#pragma unroll
    for (int i = 0; i < 8; i++) { acc01[i] = 0ull; acc23[i] = 0ull; }

#pragma unroll
    for (int kt = 0; kt < 2; kt++) {
#pragma unroll
        for (int i = 0; i < 8; i++) {
            int idx = tid + 256 * i;                   // 0..2047
            Wsh4[idx] = W4[(kt * 64 + (idx >> 5)) * 32 + (idx & 31)];
        }
#pragma unroll
        for (int i = 0; i < 4; i++) {
            int idx = tid + 256 * i;                   // 0..1023
            int n = nb + (idx >> 4);
            Ash4[idx] = (n < N_NODES) ? A4[n * 32 + kt * 16 + (idx & 15)]
                                      : make_float4(0.f, 0.f, 0.f, 0.f);
        }
        __syncthreads();

#pragma unroll 4
        for (int k = 0; k < 64; k += 2) {
            ulonglong2 wa = *(const ulonglong2*)&Wsh[k * 128 + jt * 4];
            ulonglong2 wb = *(const ulonglong2*)&Wsh[(k + 1) * 128 + jt * 4];
#pragma unroll
            for (int i = 0; i < 8; i++) {
                const float* arow = &Ash[(nt * 8 + i) * 64 + k];
                unsigned int a0 = __float_as_uint(arow[0]);
                unsigned int a1 = __float_as_uint(arow[1]);
                unsigned long long a00, a11;
                asm("mov.b64 %0, {%1, %1};" : "=l"(a00) : "r"(a0));
                asm("mov.b64 %0, {%1, %1};" : "=l"(a11) : "r"(a1));
                asm("fma.rn.f32x2 %0, %1, %2, %0;" : "+l"(acc01[i]) : "l"(a00), "l"(wa.x));
                asm("fma.rn.f32x2 %0, %1, %2, %0;" : "+l"(acc23[i]) : "l"(a00), "l"(wa.y));
                asm("fma.rn.f32x2 %0, %1, %2, %0;" : "+l"(acc01[i]) : "l"(a11), "l"(wb.x));
                asm("fma.rn.f32x2 %0, %1, %2, %0;" : "+l"(acc23[i]) : "l"(a11), "l"(wb.y));
            }
        }
        __syncthreads();
    }

    float4 bv = __ldg(&((const float4*)bias)[jt]);
#pragma unroll
    for (int i = 0; i < 8; i++) {
        int n = nb + nt * 8 + i;
        if (n < N_NODES) {
            unsigned int r01lo, r01hi, r23lo, r23hi;
            asm("mov.b64 {%0, %1}, %2;" : "=r"(r01lo), "=r"(r01hi) : "l"(acc01[i]));
            asm("mov.b64 {%0, %1}, %2;" : "=r"(r23lo), "=r"(r23hi) : "l"(acc23[i]));
            float4 r;
            r.x = fmaxf(__uint_as_float(r01lo) + bv.x, 0.f);
            r.y = fmaxf(__uint_as_float(r01hi) + bv.y, 0.f);
            r.z = fmaxf(__uint_as_float(r23lo) + bv.z, 0.f);
            r.w = fmaxf(__uint_as_float(r23hi) + bv.w, 0.f);
            ((float4*)g_bufB)[n * 32 + jt] = r;
        }
    }
}

// ---------------- per-graph mean pooling (graph_ids sorted) -----------------
__global__ void k_pool(const int* __restrict__ gid, float* __restrict__ out) {
    int g = blockIdx.x;
    int j = threadIdx.x;      // 128 threads = feature dims
    int lo = 0, hi = N_NODES;
    while (lo < hi) { int mid = (lo + hi) >> 1; if (gid[mid] < g) lo = mid + 1; else hi = mid; }
    int s = lo;
    lo = s; hi = N_NODES;
    while (lo < hi) { int mid = (lo + hi) >> 1; if (gid[mid] < g + 1) lo = mid + 1; else hi = mid; }
    int e = lo;
    float sum = 0.f;
    for (int n = s; n < e; n++) sum += g_bufB[n * D + j];
    float cnt = (float)max(e - s, 1);
    out[g * D + j] = sum / cnt;
}

// ---------------- launch ----------------------------------------------------
extern "C" void kernel_launch(void* const* d_in, const int* in_sizes, int n_in,
                              void* d_out, int out_size) {
    const float* feats = (const float*)d_in[0];
    const float* W1    = (const float*)d_in[1];
    const float* b1    = (const float*)d_in[2];
    const float* W2    = (const float*)d_in[3];
    const float* b2    = (const float*)d_in[4];
    const int*   src   = (const int*)d_in[5];
    const int*   dst   = (const int*)d_in[6];
    const int*   gid   = (const int*)d_in[7];
    float* out = (float*)d_out;

    const int TB = 256;
    int nodeBlocks = (N_NODES + TB - 1) / TB;     // 196
    int edgeBlocks = (N_EDGES + TB - 1) / TB;     // 2344
    int aggBlocks  = (N_NODES + 7) / 8;           // 6250
    int gemmBlocks = (N_NODES + 63) / 64;         // 782

    // graph preprocessing (degrees + parallel scan + norms + CSR by dst)
    k_zero_deg<<<nodeBlocks, TB>>>();
    k_degree<<<edgeBlocks, TB>>>(src, dst);
    k_scan_a<<<SCAN_BLOCKS, 1024>>>();
    k_scan_c<<<SCAN_BLOCKS, 1024>>>();
    k_scatter<<<edgeBlocks, TB>>>(src, dst);

    // layer 1
    k_agg<0><<<aggBlocks, TB>>>(feats);
    k_gemm<<<gemmBlocks, TB>>>(W1, b1);
    // layer 2
    k_agg<1><<<aggBlocks, TB>>>(feats);
    k_gemm<<<gemmBlocks, TB>>>(W2, b2);

    // pooling
    k_pool<<<N_GRAPHS, D>>>(gid, out);
}